// round 2
// baseline (speedup 1.0000x reference)
#include <cuda_runtime.h>
#include <cuda_bf16.h>
#include <math.h>

#define N 8192
#define EPS 1e-5f
#define FACT 2.0f
#define PD_EPS 1e-6f
#define CUTOFF 25.0f

#define ROWS_PER_WARP 4
#define WARPS_PER_CTA 16
#define THREADS (WARPS_PER_CTA * 32)
#define ROWS_PER_CTA (ROWS_PER_WARP * WARPS_PER_CTA)  // 64
#define NUM_CTAS (N / ROWS_PER_CTA)                   // 128

// scratch for per-row pairwise distances (deterministic 2nd-kernel reduce)
__device__ float g_pd[N];

__global__ __launch_bounds__(THREADS, 1)
void soft_knn_kernel(const float* __restrict__ pc1,
                     const float* __restrict__ pc2,
                     float* __restrict__ out) {
    extern __shared__ float4 sp[];  // N entries: {x, y, z, x^2+y^2+z^2}

    const int tid = threadIdx.x;

    // Stage pc2 into shared once per CTA (coalesced)
    for (int j = tid; j < N; j += THREADS) {
        float x = pc2[j];
        float y = pc2[N + j];
        float z = pc2[2 * N + j];
        sp[j] = make_float4(x, y, z, fmaf(x, x, fmaf(y, y, z * z)));
    }
    __syncthreads();

    const int warp = tid >> 5;
    const int lane = tid & 31;
    const int row0 = blockIdx.x * ROWS_PER_CTA + warp * ROWS_PER_WARP;

    float x1[ROWS_PER_WARP], y1[ROWS_PER_WARP], z1[ROWS_PER_WARP], s1[ROWS_PER_WARP];
#pragma unroll
    for (int r = 0; r < ROWS_PER_WARP; r++) {
        int i = row0 + r;
        x1[r] = pc1[i];
        y1[r] = pc1[N + i];
        z1[r] = pc1[2 * N + i];
        s1[r] = fmaf(x1[r], x1[r], fmaf(y1[r], y1[r], z1[r] * z1[r]));
    }

    // -------- Pass 1: find max of v = 2*dot - |p2|^2  (<=> min d2 = s1 - v) --------
    float vmax[ROWS_PER_WARP];
#pragma unroll
    for (int r = 0; r < ROWS_PER_WARP; r++) vmax[r] = -3.4e38f;

    for (int j = lane; j < N; j += 32) {
        float4 p = sp[j];
#pragma unroll
        for (int r = 0; r < ROWS_PER_WARP; r++) {
            float dot = fmaf(x1[r], p.x, fmaf(y1[r], p.y, z1[r] * p.z));
            float v = fmaf(2.0f, dot, -p.w);
            vmax[r] = fmaxf(vmax[r], v);
        }
    }
#pragma unroll
    for (int r = 0; r < ROWS_PER_WARP; r++) {
#pragma unroll
        for (int ofs = 16; ofs > 0; ofs >>= 1)
            vmax[r] = fmaxf(vmax[r], __shfl_xor_sync(0xFFFFFFFFu, vmax[r], ofs));
    }

    // Softmax max m and qualification threshold on v.
    // CRITICAL: clamp vth to vmax so the argmax point ALWAYS qualifies under
    // fp rounding (v >= vth with v == vmax). Prevents sw==0 -> 0*inf = NaN.
    float m[ROWS_PER_WARP], vth[ROWS_PER_WARP];
#pragma unroll
    for (int r = 0; r < ROWS_PER_WARP; r++) {
        float mind2 = s1[r] - vmax[r];
        float mm = FACT / fmaxf(mind2, EPS);
        m[r] = mm;
        // qualify if arg >= m - CUTOFF  <=>  d2 <= FACT/(m-CUTOFF)  <=>  v >= s1 - thresh
        float t = (mm > CUTOFF) ? (s1[r] - FACT / (mm - CUTOFF)) : -3.4e38f;
        vth[r] = fminf(t, vmax[r]);
    }

    // -------- Pass 2: accumulate softmax-weighted pc2 (exp only where it matters) ----
    float sw[ROWS_PER_WARP], ax[ROWS_PER_WARP], ay[ROWS_PER_WARP], az[ROWS_PER_WARP];
#pragma unroll
    for (int r = 0; r < ROWS_PER_WARP; r++) { sw[r] = 0.f; ax[r] = 0.f; ay[r] = 0.f; az[r] = 0.f; }

    for (int j = lane; j < N; j += 32) {
        float4 p = sp[j];
#pragma unroll
        for (int r = 0; r < ROWS_PER_WARP; r++) {
            float dot = fmaf(x1[r], p.x, fmaf(y1[r], p.y, z1[r] * p.z));
            float v = fmaf(2.0f, dot, -p.w);
            if (v >= vth[r]) {  // rare path: exp contributes non-negligibly
                float d2 = s1[r] - v;
                float arg = FACT / fmaxf(d2, EPS);
                float w = __expf(arg - m[r]);
                sw[r] += w;
                ax[r] = fmaf(w, p.x, ax[r]);
                ay[r] = fmaf(w, p.y, ay[r]);
                az[r] = fmaf(w, p.z, az[r]);
            }
        }
    }

    // Warp reductions (butterfly; result in all lanes)
#pragma unroll
    for (int r = 0; r < ROWS_PER_WARP; r++) {
#pragma unroll
        for (int ofs = 16; ofs > 0; ofs >>= 1) {
            sw[r] += __shfl_xor_sync(0xFFFFFFFFu, sw[r], ofs);
            ax[r] += __shfl_xor_sync(0xFFFFFFFFu, ax[r], ofs);
            ay[r] += __shfl_xor_sync(0xFFFFFFFFu, ay[r], ofs);
            az[r] += __shfl_xor_sync(0xFFFFFFFFu, az[r], ofs);
        }
    }

    // Lanes 0..3 each finalize one row (parallel epilogue)
    if (lane < ROWS_PER_WARP) {
        int r = lane;
        int i = row0 + r;
        float inv = 1.0f / sw[r];
        float px = ax[r] * inv;
        float py = ay[r] * inv;
        float pz = az[r] * inv;
        out[i] = px;
        out[N + i] = py;
        out[2 * N + i] = pz;
        float dx = x1[r] - px + PD_EPS;
        float dy = y1[r] - py + PD_EPS;
        float dz = z1[r] - pz + PD_EPS;
        g_pd[i] = sqrtf(fmaf(dx, dx, fmaf(dy, dy, dz * dz)));
    }
}

__global__ void mean_kernel(float* __restrict__ out, int out_size) {
    __shared__ float ss[256];
    float acc = 0.f;
    for (int i = threadIdx.x; i < N; i += 256) acc += g_pd[i];
    ss[threadIdx.x] = acc;
    __syncthreads();
    for (int o = 128; o > 0; o >>= 1) {
        if (threadIdx.x < o) ss[threadIdx.x] += ss[threadIdx.x + o];
        __syncthreads();
    }
    if (threadIdx.x == 0 && out_size > 3 * N) out[3 * N] = ss[0] * (1.0f / N);
}

extern "C" void kernel_launch(void* const* d_in, const int* in_sizes, int n_in,
                              void* d_out, int out_size) {
    const float* pc1 = (const float*)d_in[0];
    const float* pc2 = (const float*)d_in[1];
    float* out = (float*)d_out;

    cudaFuncSetAttribute(soft_knn_kernel,
                         cudaFuncAttributeMaxDynamicSharedMemorySize,
                         N * (int)sizeof(float4));

    soft_knn_kernel<<<NUM_CTAS, THREADS, N * sizeof(float4)>>>(pc1, pc2, out);
    mean_kernel<<<1, 256>>>(out, out_size);
}